// round 4
// baseline (speedup 1.0000x reference)
#include <cuda_runtime.h>
#include <cuda_fp16.h>
#include <stdint.h>

#define NN 100000
#define EE 3200000
#define GG 1024
#define HH 16

// Scratch (device globals; no allocation allowed)
__device__ __half2 d_h0[NN * 8];   // node features, fp16, row = 32B
__device__ __half2 d_h1[NN * 8];
__device__ float d_dis[NN];
__device__ float d_cnt[GG];
__device__ int   d_edeg[NN];
__device__ int   d_row[NN];
__device__ int   d_cursor[NN];
__device__ int   d_csr[EE];
__device__ int   d_bsum[1024];
__device__ int   d_bbase[1024];

// ---------------------------------------------------------------------------
__global__ void k_init(float* __restrict__ out, const float* __restrict__ bo, int n, int g) {
    int i = blockIdx.x * blockDim.x + threadIdx.x;
    if (i < n) d_edeg[i] = 0;
    if (i < g) { d_cnt[i] = 0.0f; out[i] = bo[0]; }
}

__global__ void k_count(const int* __restrict__ dst, const int* __restrict__ batch,
                        int e, int n) {
    int i = blockIdx.x * blockDim.x + threadIdx.x;
    if (i < e) atomicAdd(&d_edeg[dst[i]], 1);
    if (i < n) atomicAdd(&d_cnt[batch[i]], 1.0f);
}

// ---- scan of d_edeg -> d_row / d_cursor; also dis = rsqrt(deg+1) ------------
#define SCAN_T 1024
__global__ void k_block_sums(int n) {
    int t = threadIdx.x;
    int i = blockIdx.x * SCAN_T + t;
    int v = (i < n) ? d_edeg[i] : 0;
#pragma unroll
    for (int off = 16; off > 0; off >>= 1) v += __shfl_xor_sync(0xffffffffu, v, off);
    __shared__ int ws[32];
    if ((t & 31) == 0) ws[t >> 5] = v;
    __syncthreads();
    if (t < 32) {
        int x = ws[t];
#pragma unroll
        for (int off = 16; off > 0; off >>= 1) x += __shfl_xor_sync(0xffffffffu, x, off);
        if (t == 0) d_bsum[blockIdx.x] = x;
    }
}

__global__ void k_scan_bsum(int nb) {
    __shared__ int sh[SCAN_T];
    int v = (threadIdx.x < nb) ? d_bsum[threadIdx.x] : 0;
    sh[threadIdx.x] = v;
    __syncthreads();
    for (int off = 1; off < SCAN_T; off <<= 1) {
        int t2 = (threadIdx.x >= off) ? sh[threadIdx.x - off] : 0;
        __syncthreads();
        sh[threadIdx.x] += t2;
        __syncthreads();
    }
    if (threadIdx.x < nb) d_bbase[threadIdx.x] = sh[threadIdx.x] - v;
}

__global__ void k_scan_local(int n) {
    int t = threadIdx.x;
    int lane = t & 31, wid = t >> 5;
    int i = blockIdx.x * SCAN_T + t;
    int v = (i < n) ? d_edeg[i] : 0;
    int sv = v;
#pragma unroll
    for (int off = 1; off < 32; off <<= 1) {
        int u = __shfl_up_sync(0xffffffffu, sv, off);
        if (lane >= off) sv += u;
    }
    __shared__ int wsum[32];
    if (lane == 31) wsum[wid] = sv;
    __syncthreads();
    if (t < 32) {
        int x = wsum[t];
        int sx = x;
#pragma unroll
        for (int off = 1; off < 32; off <<= 1) {
            int u = __shfl_up_sync(0xffffffffu, sx, off);
            if (t >= off) sx += u;
        }
        wsum[t] = sx - x;  // exclusive warp bases
    }
    __syncthreads();
    if (i < n) {
        int excl = sv - v + wsum[wid] + d_bbase[blockIdx.x];
        d_row[i] = excl;
        d_cursor[i] = excl;
        d_dis[i] = rsqrtf((float)v + 1.0f);
    }
}

__global__ void k_fill(const int* __restrict__ src, const int* __restrict__ dst, int e) {
    int i = blockIdx.x * blockDim.x + threadIdx.x;
    if (i >= e) return;
    int d = dst[i];
    int p = atomicAdd(&d_cursor[d], 1);
    d_csr[p] = src[i];
}

// ---------------------------------------------------------------------------
// Layer 0: embed + (x @ Wg0) * dis -> h0 (fp16).  One thread per node.
__global__ void k_layer0(const int* __restrict__ types, const int* __restrict__ pos,
                         const float* __restrict__ W1, const float* __restrict__ b1,
                         const float* __restrict__ W2, const float* __restrict__ b2,
                         const float* __restrict__ Wg0,
                         __half2* __restrict__ h_out, int n) {
    __shared__ float sW1[3 * HH], sb1[HH], sW2[3 * HH], sb2[HH], sW[32 * HH];
    int t = threadIdx.x;
    if (t < 48) { sW1[t] = W1[t]; sW2[t] = W2[t]; }
    if (t < 16) { sb1[t] = b1[t]; sb2[t] = b2[t]; }
    for (int i = t; i < 32 * HH; i += blockDim.x) sW[i] = Wg0[i];
    __syncthreads();

    int nidx = blockIdx.x * blockDim.x + t;
    if (nidx >= n) return;

    int ty = types[nidx], pp = pos[nidx];
    float x[32];
#pragma unroll
    for (int j = 0; j < 16; j++) {
        x[j]      = sW1[ty * 16 + j] + sb1[j];
        x[16 + j] = sW2[pp * 16 + j] + sb2[j];
    }
    float acc[16];
#pragma unroll
    for (int j = 0; j < 16; j++) acc[j] = 0.0f;
#pragma unroll
    for (int i = 0; i < 32; i++) {
        float xi = x[i];
#pragma unroll
        for (int j = 0; j < 16; j++) acc[j] = fmaf(xi, sW[i * 16 + j], acc[j]);
    }
    float ds = d_dis[nidx];
    __half2 o[8];
#pragma unroll
    for (int k = 0; k < 8; k++)
        o[k] = __float22half2_rn(make_float2(acc[2 * k] * ds, acc[2 * k + 1] * ds));
    uint4* dstp = (uint4*)(h_out + (size_t)nidx * 8);
    dstp[0] = *(uint4*)&o[0];
    dstp[1] = *(uint4*)&o[4];
}

// ---------------------------------------------------------------------------
// Aggregate (CSR gather, fp16 rows) + transform. One lane-PAIR per node; each
// lane owns 8 channels. fp32 accumulation + matvec.
__device__ __forceinline__ void acc8(float* s, uint4 u) {
    const __half2* h = (const __half2*)&u;
#pragma unroll
    for (int k = 0; k < 4; k++) {
        float2 f = __half22float2(h[k]);
        s[2 * k] += f.x; s[2 * k + 1] += f.y;
    }
}

__global__ void k_agg_layer(const __half2* __restrict__ h_in,
                            const float* __restrict__ W, const float* __restrict__ b_prev,
                            __half2* __restrict__ h_out, int n) {
    __shared__ float sW[16 * HH], sb[HH];
    int t = threadIdx.x;
    if (t < 16 * HH) sW[t] = W[t];
    if (t < HH) sb[t] = b_prev[t];
    __syncthreads();

    int gid = blockIdx.x * blockDim.x + t;
    int node_raw = gid >> 1;
    bool valid = node_raw < n;
    int node = valid ? node_raw : (n - 1);
    int p = t & 1;
    unsigned pmask = 3u << ((t & 31) & ~1);

    int base = d_row[node];
    int deg  = d_edeg[node];

    float s[8];
    {   // self term
        uint4 u = *((const uint4*)(h_in + (size_t)node * 8) + p);
        const __half2* h = (const __half2*)&u;
#pragma unroll
        for (int k = 0; k < 4; k++) {
            float2 f = __half22float2(h[k]);
            s[2 * k] = f.x; s[2 * k + 1] = f.y;
        }
    }

    int j = 0;
    for (; j + 2 <= deg; j += 2) {
        int myidx = d_csr[base + j + p];
#pragma unroll
        for (int r = 0; r < 2; r++) {
            int id = __shfl_sync(pmask, myidx, r, 2);
            uint4 u = *((const uint4*)(h_in + (size_t)id * 8) + p);
            acc8(s, u);
        }
    }
    if (j < deg) {
        int id = d_csr[base + j];   // both lanes converged, same load
        uint4 u = *((const uint4*)(h_in + (size_t)id * 8) + p);
        acc8(s, u);
    }

    float ds = d_dis[node];
    float x[8];
#pragma unroll
    for (int k = 0; k < 8; k++)
        x[k] = fmaxf(fmaf(ds, s[k], sb[p * 8 + k]), 0.0f);

    float acc[8];
#pragma unroll
    for (int k = 0; k < 8; k++) acc[k] = 0.0f;
#pragma unroll
    for (int r = 0; r < 2; r++) {
        float y[8];
#pragma unroll
        for (int k = 0; k < 8; k++) y[k] = __shfl_sync(pmask, x[k], r, 2);
#pragma unroll
        for (int i = 0; i < 8; i++) {
            const float* wrow = &sW[(r * 8 + i) * 16 + p * 8];
#pragma unroll
            for (int k = 0; k < 8; k++) acc[k] = fmaf(y[i], wrow[k], acc[k]);
        }
    }

    if (valid) {
        __half2 o[4];
#pragma unroll
        for (int k = 0; k < 4; k++)
            o[k] = __float22half2_rn(make_float2(acc[2 * k] * ds, acc[2 * k + 1] * ds));
        *((uint4*)(h_out + (size_t)node * 8) + p) = *(uint4*)&o[0];
    }
}

// Last layer: aggregate + (dis*sum + bg2) . Wo, mean-pool into out[batch].
__global__ void k_agg_pool(const __half2* __restrict__ h_in,
                           const float* __restrict__ bg2, const float* __restrict__ Wo,
                           const int* __restrict__ batch, float* __restrict__ out, int n) {
    __shared__ float sb[HH], sw[HH];
    int t = threadIdx.x;
    if (t < HH) { sb[t] = bg2[t]; sw[t] = Wo[t]; }
    __syncthreads();

    int gid = blockIdx.x * blockDim.x + t;
    int node_raw = gid >> 1;
    bool valid = node_raw < n;
    int node = valid ? node_raw : (n - 1);
    int p = t & 1;
    unsigned pmask = 3u << ((t & 31) & ~1);

    int base = d_row[node];
    int deg  = d_edeg[node];

    float s[8];
    {
        uint4 u = *((const uint4*)(h_in + (size_t)node * 8) + p);
        const __half2* h = (const __half2*)&u;
#pragma unroll
        for (int k = 0; k < 4; k++) {
            float2 f = __half22float2(h[k]);
            s[2 * k] = f.x; s[2 * k + 1] = f.y;
        }
    }

    int j = 0;
    for (; j + 2 <= deg; j += 2) {
        int myidx = d_csr[base + j + p];
#pragma unroll
        for (int r = 0; r < 2; r++) {
            int id = __shfl_sync(pmask, myidx, r, 2);
            uint4 u = *((const uint4*)(h_in + (size_t)id * 8) + p);
            acc8(s, u);
        }
    }
    if (j < deg) {
        int id = d_csr[base + j];
        uint4 u = *((const uint4*)(h_in + (size_t)id * 8) + p);
        acc8(s, u);
    }

    float ds = d_dis[node];
    float pp = 0.0f;
#pragma unroll
    for (int k = 0; k < 8; k++)
        pp = fmaf(fmaf(ds, s[k], sb[p * 8 + k]), sw[p * 8 + k], pp);
    pp += __shfl_xor_sync(pmask, pp, 1, 2);

    // Full warp reconverged here (no early returns above).
    int g = batch[node];
    float c = fmaxf(d_cnt[g], 1.0f);
    float contrib = (p == 0 && valid) ? pp / c : 0.0f;

    int g0 = __shfl_sync(0xffffffffu, g, 0);
    bool uni = __all_sync(0xffffffffu, g == g0);
    if (uni) {
#pragma unroll
        for (int off = 16; off > 0; off >>= 1)
            contrib += __shfl_xor_sync(0xffffffffu, contrib, off);
        if ((t & 31) == 0) atomicAdd(&out[g0], contrib);
    } else {
        if (p == 0 && valid) atomicAdd(&out[g], contrib);
    }
}

// ---------------------------------------------------------------------------
extern "C" void kernel_launch(void* const* d_in, const int* in_sizes, int n_in,
                              void* d_out, int out_size) {
    const int*   types = (const int*)d_in[0];
    const int*   pos   = (const int*)d_in[1];
    const int*   eidx  = (const int*)d_in[2];
    const int*   batch = (const int*)d_in[3];
    const float* W1  = (const float*)d_in[4];
    const float* b1  = (const float*)d_in[5];
    const float* W2  = (const float*)d_in[6];
    const float* b2  = (const float*)d_in[7];
    const float* Wg0 = (const float*)d_in[8];
    const float* bg0 = (const float*)d_in[9];
    const float* Wg1 = (const float*)d_in[10];
    const float* bg1 = (const float*)d_in[11];
    const float* Wg2 = (const float*)d_in[12];
    const float* bg2 = (const float*)d_in[13];
    const float* Wo  = (const float*)d_in[14];
    const float* bo  = (const float*)d_in[15];
    float* out = (float*)d_out;

    const int n = in_sizes[0];
    const int e = in_sizes[2] / 2;
    const int g = out_size;
    const int* src = eidx;
    const int* dst = eidx + e;

    __half2 *h0, *h1;
    cudaGetSymbolAddress((void**)&h0, d_h0);
    cudaGetSymbolAddress((void**)&h1, d_h1);

    const int BT = 256;
    dim3 gN((n + BT - 1) / BT);
    dim3 gE((e + BT - 1) / BT);
    dim3 gP(((n * 2) + BT - 1) / BT);    // pair-per-node kernels
    int nb = (n + SCAN_T - 1) / SCAN_T;

    k_init<<<gN, BT>>>(out, bo, n, g);
    k_count<<<gE, BT>>>(dst, batch, e, n);

    // CSR build (+ dis fused into scan_local)
    k_block_sums<<<nb, SCAN_T>>>(n);
    k_scan_bsum<<<1, SCAN_T>>>(nb);
    k_scan_local<<<nb, SCAN_T>>>(n);
    k_fill<<<gE, BT>>>(src, dst, e);

    // layer 0 (embed fused)
    k_layer0<<<gN, BT>>>(types, pos, W1, b1, W2, b2, Wg0, h0, n);
    // layers 1,2 fused agg+transform
    k_agg_layer<<<gP, BT>>>(h0, Wg1, bg0, h1, n);
    k_agg_layer<<<gP, BT>>>(h1, Wg2, bg1, h0, n);
    // last aggregation fused with pool
    k_agg_pool<<<gP, BT>>>(h0, bg2, Wo, batch, out, n);
}